// round 13
// baseline (speedup 1.0000x reference)
#include <cuda_runtime.h>

// SamplingLayer: out[b, p*64+k] = sum_l x[b, p*1024+l] * exp(-((l+1)-w_k)^2/100)
// Gaussian band (std=10): per k-PAIR union window of 80 floats; W regenerated
// in registers via packed f32x2 multiplicative recurrence (zero W traffic).
// R12: persistent grid-stride blocks with cp.async (LDGSTS) DOUBLE-BUFFERED
// tile pipeline. R10/R11 both plateaued at ~121us with every pipe <=60%:
// the stage->sync->compute phase lockstep capped DRAM duty at the stage
// fraction. Async staging of tile i+1 overlaps tile i's compute -> DRAM
// stays busy continuously.

#define NUM_P   8
#define DLEN    1024
#define KT      64          // L_tilde
#define WS      64          // core window per k
#define ULEN    80          // union window per k-pair (floats)
#define UJ      (ULEN/4)    // 20 float4 steps
#define ROWS    8           // (b,p) rows per tile (per pipeline buffer)
#define STRIDE  1028        // padded smem row stride (16B-bank conflict-free for 8 lanes)
#define OSTRIDE 68          // padded output staging stride
#define THREADS 256
#define GRID    444         // 148 SMs x 3 resident blocks
#define NTILES  ((16384 * NUM_P) / ROWS)   // 16384

__device__ float4 g_init[KT];     // per k: (w0, w0*q0, q0^2*r, q0^2*r^3) seeded at ubase
__device__ int    g_ubase[KT/2];  // per k-pair union base

// Precompute union bases + packed recurrence seeds. Deterministic, re-run
// every launch; trivial cost.
__global__ void precompute_kernel(const float* __restrict__ w) {
    __shared__ int bases[KT];
    int k = threadIdx.x;
    float wk = w[k];
    int base = (int)rintf(wk) - 33;           // center 64-window: t = base+1..base+64
    base &= ~3;                                // 16B alignment
    base = max(0, min(base, DLEN - WS));
    bases[k] = base;
    __syncthreads();
    int kg = k >> 1;
    int ub = min(bases[kg * 2], DLEN - ULEN);  // union covers both pair members
    if ((k & 1) == 0) g_ubase[kg] = ub;
    float d0 = (float)(ub + 1) - wk;
    float w0 = expf(-d0 * d0 * 0.01f);
    float q0 = expf(-(2.0f * d0 + 1.0f) * 0.01f);
    const float r = 0.98019867330675525f;      // exp(-0.02)
    float s0 = q0 * q0 * r;                    // q_0*q_1
    float s1 = s0 * r * r;                     // q_1*q_2
    g_init[k] = make_float4(w0, w0 * q0, s0, s1);
}

__device__ __forceinline__ unsigned long long pack2(float lo, float hi) {
    return ((unsigned long long)__float_as_uint(hi) << 32) |
           (unsigned long long)__float_as_uint(lo);
}
__device__ __forceinline__ float hsum2(unsigned long long v) {
    return __uint_as_float((unsigned int)v) + __uint_as_float((unsigned int)(v >> 32));
}

__global__ void __launch_bounds__(THREADS, 3)
sampling_main_kernel(const float* __restrict__ x, float* __restrict__ out) {
    __shared__ __align__(16) float x_s[2][ROWS * STRIDE];   // 2 x 32896 B
    __shared__ float  out_s[ROWS * OSTRIDE];                // 2176 B
    __shared__ float4 init_s[KT];
    __shared__ int    ub_s[KT / 2];

    const int t = threadIdx.x;
    if (t < KT) init_s[t] = g_init[t];
    if (t < KT / 2) ub_s[t] = g_ubase[t];
    __syncthreads();

    // ---- per-thread constants ----
    const int r0 = t & (ROWS - 1);    // 0..7
    const int kg = t >> 3;            // 0..31 k-pairs
    const int ub = ub_s[kg];

    float4 p0 = init_s[kg * 2];       // recurrence seeds, kept in registers
    float4 p1 = init_s[kg * 2 + 1];

    const float r4 = 0.92311634638663577f;   // exp(-0.08)
    const unsigned long long R4 =
        (unsigned long long)__float_as_uint(r4) * 0x100000001ULL;  // (r4, r4)

    // staging: iteration i stages row i, 16B chunk t (256 chunks per row)
    const unsigned int s_dst0 =
        (unsigned int)__cvta_generic_to_shared(&x_s[0][0]) + (unsigned int)t * 16u;
    const unsigned int lds_off0 =
        (unsigned int)__cvta_generic_to_shared(&x_s[0][r0 * STRIDE + ub]);

    // ---- prologue: stage first tile into buffer 0 ----
    int tile = blockIdx.x;
    {
        const float4* src = (const float4*)(x + (size_t)tile * (ROWS * DLEN)) + t;
        unsigned int dst = s_dst0;
        #pragma unroll
        for (int i = 0; i < ROWS; i++) {
            asm volatile("cp.async.cg.shared.global [%0], [%1], 16;"
                         :: "r"(dst), "l"(src) : "memory");
            dst += STRIDE * 4;
            src += DLEN / 4;
        }
    }
    asm volatile("cp.async.commit_group;" ::: "memory");

    int buf = 0;
    for (; tile < NTILES; tile += GRID, buf ^= 1) {
        // ---- stage NEXT tile into the other buffer (overlaps this compute) ----
        int nxt = tile + GRID;
        if (nxt < NTILES) {
            const float4* src = (const float4*)(x + (size_t)nxt * (ROWS * DLEN)) + t;
            unsigned int dst = s_dst0 + (unsigned int)(buf ^ 1) * (ROWS * STRIDE * 4);
            #pragma unroll
            for (int i = 0; i < ROWS; i++) {
                asm volatile("cp.async.cg.shared.global [%0], [%1], 16;"
                             :: "r"(dst), "l"(src) : "memory");
                dst += STRIDE * 4;
                src += DLEN / 4;
            }
        }
        asm volatile("cp.async.commit_group;" ::: "memory");
        asm volatile("cp.async.wait_group 1;" ::: "memory");  // current buf ready
        __syncthreads();

        // ---- compute from x_s[buf]: 20 x (LDS.128 + 12 packed f32x2 ops) ----
        unsigned long long W2[2], S2[2];
        W2[0] = pack2(p0.x, p0.y);  S2[0] = pack2(p0.z, p0.w);
        W2[1] = pack2(p1.x, p1.y);  S2[1] = pack2(p1.z, p1.w);
        unsigned long long acc[2] = {0ULL, 0ULL};

        unsigned int lds = lds_off0 + (unsigned int)buf * (ROWS * STRIDE * 4);
        #pragma unroll
        for (int j = 0; j < UJ; j++) {
            unsigned long long xlo, xhi;
            asm volatile("ld.shared.v2.b64 {%0, %1}, [%2];"
                         : "=l"(xlo), "=l"(xhi) : "r"(lds + j * 16u));
            #pragma unroll
            for (int kk = 0; kk < 2; kk++) {
                asm("fma.rn.f32x2 %0, %1, %2, %0;" : "+l"(acc[kk]) : "l"(xlo), "l"(W2[kk]));
                asm("mul.rn.f32x2 %0, %0, %1;"     : "+l"(W2[kk])  : "l"(S2[kk]));
                asm("mul.rn.f32x2 %0, %0, %1;"     : "+l"(S2[kk])  : "l"(R4));
                asm("fma.rn.f32x2 %0, %1, %2, %0;" : "+l"(acc[kk]) : "l"(xhi), "l"(W2[kk]));
                asm("mul.rn.f32x2 %0, %0, %1;"     : "+l"(W2[kk])  : "l"(S2[kk]));
                asm("mul.rn.f32x2 %0, %0, %1;"     : "+l"(S2[kk])  : "l"(R4));
            }
        }

        // ---- transpose-stage outputs in smem, then coalesced store ----
        *(float2*)&out_s[r0 * OSTRIDE + kg * 2] =
            make_float2(hsum2(acc[0]), hsum2(acc[1]));
        __syncthreads();

        if (t < (ROWS * KT / 4)) {        // 128 float4 stores
            float4* __restrict__ og = (float4*)(out + (size_t)tile * (ROWS * KT));
            int r2 = t >> 4;              // row within tile
            int c2 = t & 15;              // float4 column
            og[t] = *(float4*)&out_s[r2 * OSTRIDE + c2 * 4];
        }
        // next iteration's post-wait __syncthreads isolates out_s reuse
    }
}

extern "C" void kernel_launch(void* const* d_in, const int* in_sizes, int n_in,
                              void* d_out, int out_size) {
    const float* x = (const float*)d_in[0];      // [16384, 8192] fp32
    const float* w = (const float*)d_in[1];      // [64] fp32
    float* out = (float*)d_out;                  // [16384, 512] fp32

    precompute_kernel<<<1, KT>>>(w);
    sampling_main_kernel<<<GRID, THREADS>>>(x, out);
}